// round 2
// baseline (speedup 1.0000x reference)
#include <cuda_runtime.h>
#include <math_constants.h>
#include <cstdint>

// ---------------------------------------------------------------------------
// SoftmaxMatcherBlock: fused flash-attention-style matcher.
//   B=2, C=256, N=1024 (queries), M=65536 (keys), V-dim = 260 (3+1+256).
// Pipeline:
//   init_kernel   : zero the max_softmax slots
//   stats_kernel  : per-key mean + alpha = 100/(256*std) (ddof=1)
//   srcsum_kernel : per-query sum over C of src (for exact mean-correction)
//   flash_kernel  : split-M online softmax; logits fp32 GEMM + P@V fp32 GEMM
//   combine_kernel: merge splits, normalize, zn(desc), 2D proj, valid, maxsoft
//
// Algebra: logit(n,m) = alpha_m * (dot(src_n, tgt_m) - mu_m * sum_c src_cn)
// with alpha_m = (1/0.01) / (C * std_m). This avoids materializing the
// normalized key matrix and the 512 MiB score matrix.
// ---------------------------------------------------------------------------

#define B_ 2
#define C_ 256
#define N_ 1024
#define M_ 65536
#define BN 64
#define BM 128
#define SPLITS 8
#define NT (N_ / BN)            // 16
#define MSLICE (M_ / SPLITS)    // 8192
#define ITERS (MSLICE / BM)     // 64
#define VD 272                  // 260 real channels padded to 272 (4*68)
#define VD2 274                 // mu, Z, 272 accum
#define PS_STRIDE 132           // P tile row stride (pad to kill bank conflicts)

#define OFF_COORDS 0
#define OFF_W      6144
#define OFF_DESC   8192
#define OFF_2D     532480
#define OFF_VALID  536576
#define OFF_MAX    538624

#define CART_MIN 33.048f        // (256/2 - 0.5) * 0.2592
#define RES_     0.2592f

// Device scratch (static allocations are allowed; cudaMalloc is not).
__device__ float g_alpha[B_ * M_];
__device__ float g_mu[B_ * M_];
__device__ float g_ssum[B_ * N_];
__device__ float g_part[(size_t)B_ * SPLITS * NT * BN * VD2];  // ~17 MiB

// ---------------------------------------------------------------------------
__global__ void init_kernel(float* __restrict__ out) {
    if (threadIdx.x < 2) out[OFF_MAX + threadIdx.x] = 0.0f;
}

// Per (b,m): mean over C and alpha = (100/256)/std (ddof=1).
__global__ void stats_kernel(const float* __restrict__ tgt_desc) {
    int gid = blockIdx.x * blockDim.x + threadIdx.x;
    if (gid >= B_ * M_) return;
    int b = gid / M_;
    int m = gid - b * M_;
    const float* p = tgt_desc + (size_t)b * C_ * M_ + m;
    float s = 0.f, s2 = 0.f;
#pragma unroll 8
    for (int c = 0; c < C_; c++) {
        float t = p[(size_t)c * M_];
        s += t;
        s2 += t * t;
    }
    float mean = s * (1.0f / C_);
    float var = (s2 - (float)C_ * mean * mean) * (1.0f / (C_ - 1));
    g_mu[gid] = mean;
    g_alpha[gid] = (100.0f / C_) / sqrtf(var);
}

// Per (b,n): sum over C of src_desc_norm (tiny mean-correction term).
__global__ void srcsum_kernel(const float* __restrict__ src) {
    int gid = blockIdx.x * blockDim.x + threadIdx.x;
    if (gid >= B_ * N_) return;
    int b = gid / N_;
    int n = gid - b * N_;
    const float* p = src + (size_t)b * C_ * N_ + n;
    float s = 0.f;
#pragma unroll 8
    for (int c = 0; c < C_; c++) s += p[(size_t)c * N_];
    g_ssum[gid] = s;
}

// ---------------------------------------------------------------------------
// Fused flash kernel. Grid: B * SPLITS * NT CTAs of 256 threads.
// smem (floats):
//   Ss   [C][BN]       16384      persistent query tile
//   Ts   [32][BM]       4096      staged key chunk (K-major)
//   Ps   [BN][132]      8448      exp(P) tile
//   Vs   [32][VD]       8704      staged V chunk
//   alpha/mu/ssum/rowMu/rowZ/fsc  small
__global__ void __launch_bounds__(256, 1)
flash_kernel(const float* __restrict__ src,
             const float* __restrict__ tgt_desc,
             const float* __restrict__ tgt_coords,
             const float* __restrict__ tgt_w) {
    extern __shared__ float sm[];
    float* Ss      = sm;                 // 16384
    float* Ts      = sm + 16384;         // 4096
    float* Ps      = sm + 20480;         // 8448
    float* Vs      = sm + 28928;         // 8704
    float* alpha_s = sm + 37632;         // 128
    float* mu_s    = sm + 37760;         // 128
    float* ssum_s  = sm + 37888;         // 64
    float* rowMu   = sm + 37952;         // 64
    float* rowZ    = sm + 38016;         // 64
    float* fsc     = sm + 38080;         // 64  (total 38144 floats = 152576 B)

    const int tid = threadIdx.x;
    const int bid = blockIdx.x;
    const int bb  = bid / (SPLITS * NT);
    const int rem = bid - bb * (SPLITS * NT);
    const int sp  = rem / NT;
    const int nt  = rem - sp * NT;
    const int n0  = nt * BN;
    const int mbase = sp * MSLICE;

    const int tx = tid & 15;   // m-dir (8 cols each)
    const int ty = tid >> 4;   // n-dir (4 rows each)
    const int n2 = tid >> 2;   // GEMM2 row (0..63)
    const int g  = tid & 3;    // GEMM2 col group (68 cols each)

    // Load persistent query tile Ss[c][j] = src[bb][c][n0+j]
    {
        const float* spp = src + (size_t)bb * C_ * N_ + n0;
        for (int i = tid; i < (C_ * BN) / 4; i += 256) {
            int f = i * 4;
            int c = f >> 6;
            int j = f & 63;
            *(float4*)&Ss[c * BN + j] = *(const float4*)&spp[(size_t)c * N_ + j];
        }
    }
    if (tid < BN) {
        ssum_s[tid] = g_ssum[bb * N_ + n0 + tid];
        rowMu[tid] = -CUDART_INF_F;
        rowZ[tid] = 0.0f;
    }

    float O[68];
#pragma unroll
    for (int j = 0; j < 68; j++) O[j] = 0.0f;
    __syncthreads();

    for (int it = 0; it < ITERS; it++) {
        const int m0 = mbase + it * BM;
        if (tid < BM) alpha_s[tid] = g_alpha[bb * M_ + m0 + tid];
        else          mu_s[tid - BM] = g_mu[bb * M_ + m0 + (tid - BM)];

        // ---- GEMM1: L[64][128] = Ss^T(64x256) * Ts(256x128) ----
        float L[4][8];
#pragma unroll
        for (int r = 0; r < 4; r++)
#pragma unroll
            for (int u = 0; u < 8; u++) L[r][u] = 0.0f;

        const float* tg0 = tgt_desc + (size_t)bb * C_ * M_ + m0;
#pragma unroll 1
        for (int kc = 0; kc < C_ / 32; kc++) {
            __syncthreads();
            const float* tg = tg0 + (size_t)kc * 32 * M_;
            // 4 x LDG.128 per thread, front-batched for MLP
            {
                int f0 = tid * 4;
#pragma unroll
                for (int q = 0; q < 4; q++) {
                    int f = f0 + q * 1024;
                    int kk = f >> 7;
                    int mm = f & 127;
                    *(float4*)&Ts[kk * BM + mm] =
                        *(const float4*)&tg[(size_t)kk * M_ + mm];
                }
            }
            __syncthreads();
#pragma unroll
            for (int k = 0; k < 32; k++) {
                float4 a4 = *(float4*)&Ss[(kc * 32 + k) * BN + (ty << 2)];
                float4 b4 = *(float4*)&Ts[k * BM + (tx << 3)];
                float4 b5 = *(float4*)&Ts[k * BM + (tx << 3) + 4];
                float av[4] = {a4.x, a4.y, a4.z, a4.w};
                float bv[8] = {b4.x, b4.y, b4.z, b4.w, b5.x, b5.y, b5.z, b5.w};
#pragma unroll
                for (int r = 0; r < 4; r++)
#pragma unroll
                    for (int u = 0; u < 8; u++) L[r][u] += av[r] * bv[u];
            }
        }

        // ---- finalize logits + online softmax (per row, across 16 tx) ----
#pragma unroll
        for (int r = 0; r < 4; r++) {
            int row = (ty << 2) + r;
            float ssn = ssum_s[row];
            float lv[8];
            float mloc = -CUDART_INF_F;
#pragma unroll
            for (int u = 0; u < 8; u++) {
                int cm = (tx << 3) + u;
                float l = alpha_s[cm] * (L[r][u] - mu_s[cm] * ssn);
                lv[u] = l;
                mloc = fmaxf(mloc, l);
            }
#pragma unroll
            for (int o = 8; o > 0; o >>= 1)
                mloc = fmaxf(mloc, __shfl_xor_sync(0xffffffffu, mloc, o, 16));
            float mold = rowMu[row];
            float mnew = fmaxf(mold, mloc);
            float sloc = 0.0f;
#pragma unroll
            for (int u = 0; u < 8; u++) {
                float p = __expf(lv[u] - mnew);
                Ps[row * PS_STRIDE + (tx << 3) + u] = p;
                sloc += p;
            }
#pragma unroll
            for (int o = 8; o > 0; o >>= 1)
                sloc += __shfl_xor_sync(0xffffffffu, sloc, o, 16);
            if (tx == 0) {
                float fr = __expf(mold - mnew);   // 0 on first tile (-inf)
                rowZ[row] = rowZ[row] * fr + sloc;
                rowMu[row] = mnew;
                fsc[row] = fr;
            }
        }
        __syncthreads();

        // ---- GEMM2: O[64][272] = f*O + Ps[64][128] * V[128][272] ----
        {
            float fr = fsc[n2];
#pragma unroll
            for (int j = 0; j < 68; j++) O[j] *= fr;
        }
        const int lane = tid & 31;
        const int grp = tid >> 5;
#pragma unroll 1
        for (int ck = 0; ck < 4; ck++) {
            int mg = m0 + ck * 32 + lane;
            for (int ch = grp; ch < VD; ch += 8) {
                float v;
                if (ch < 3)        v = tgt_coords[((size_t)bb * 3 + ch) * M_ + mg];
                else if (ch == 3)  v = tgt_w[(size_t)bb * M_ + mg];
                else if (ch < 260) v = tgt_desc[((size_t)bb * C_ + (ch - 4)) * M_ + mg];
                else               v = 0.0f;
                Vs[lane * VD + ch] = v;
            }
            __syncthreads();
            const float* prow = &Ps[n2 * PS_STRIDE + ck * 32];
#pragma unroll
            for (int mm = 0; mm < 32; mm++) {
                float p = prow[mm];
                const float4* vr = (const float4*)&Vs[mm * VD + g * 68];
#pragma unroll
                for (int jj = 0; jj < 17; jj++) {
                    float4 v = vr[jj];
                    O[jj * 4 + 0] += p * v.x;
                    O[jj * 4 + 1] += p * v.y;
                    O[jj * 4 + 2] += p * v.z;
                    O[jj * 4 + 3] += p * v.w;
                }
            }
            __syncthreads();
        }
    }

    // ---- write partials ----
    size_t rowidx = (((size_t)bb * SPLITS + sp) * NT + nt) * BN + n2;
    float* pp = g_part + rowidx * VD2;
    if (g == 0) {
        pp[0] = rowMu[n2];
        pp[1] = rowZ[n2];
    }
#pragma unroll
    for (int jj = 0; jj < 68; jj++) pp[2 + g * 68 + jj] = O[jj];
}

// ---------------------------------------------------------------------------
// Combine splits + all epilogue math. One warp per (b,n) row.
__global__ void combine_kernel(float* __restrict__ out) {
    const int warp = threadIdx.x >> 5;
    const int lane = threadIdx.x & 31;
    const int row = blockIdx.x * 8 + warp;      // 0..2047
    const int b = row / N_;
    const int n = row - b * N_;
    const int nt = n / BN;
    const int r = n - nt * BN;

    const float* pbase[SPLITS];
    float mu[SPLITS], Zv[SPLITS];
#pragma unroll
    for (int s = 0; s < SPLITS; s++) {
        pbase[s] = g_part +
            ((((size_t)b * SPLITS + s) * NT + nt) * BN + r) * VD2;
        mu[s] = pbase[s][0];
        Zv[s] = pbase[s][1];
    }
    float gmax = mu[0];
#pragma unroll
    for (int s = 1; s < SPLITS; s++) gmax = fmaxf(gmax, mu[s]);
    float w[SPLITS], Zt = 0.0f;
#pragma unroll
    for (int s = 0; s < SPLITS; s++) {
        w[s] = __expf(mu[s] - gmax);
        Zt += Zv[s] * w[s];
    }
    float invZ = 1.0f / Zt;

    float vals[9];
#pragma unroll
    for (int j = 0; j < 9; j++) {
        int ch = lane + 32 * j;
        float acc = 0.0f;
        if (ch < VD) {
#pragma unroll
            for (int s = 0; s < SPLITS; s++)
                acc += w[s] * pbase[s][2 + ch];
        }
        vals[j] = acc * invZ;
    }

    // coords / weight / 2D / valid / max_softmax
    if (lane < 3) out[OFF_COORDS + (b * 3 + lane) * N_ + n] = vals[0];
    if (lane == 3) out[OFF_W + b * N_ + n] = vals[0];
    float x = __shfl_sync(0xffffffffu, vals[0], 0);
    float y = __shfl_sync(0xffffffffu, vals[0], 1);
    if (lane == 0) {
        out[OFF_2D + (b * N_ + n) * 2 + 0] = (CART_MIN + y) / RES_;
        out[OFF_2D + (b * N_ + n) * 2 + 1] = (CART_MIN - x) / RES_;
    }
    if (lane == 4) out[OFF_VALID + b * N_ + n] = 1.0f;
    if (lane == 5)
        atomicMax((int*)(out + OFF_MAX + b), __float_as_int(invZ));

    // zn over the 256 desc channels (ch in [4,260)); ddof=1
    float s1 = 0.0f, s2 = 0.0f;
#pragma unroll
    for (int j = 0; j < 9; j++) {
        int ch = lane + 32 * j;
        if (ch >= 4 && ch < 260) {
            s1 += vals[j];
            s2 += vals[j] * vals[j];
        }
    }
#pragma unroll
    for (int o = 16; o > 0; o >>= 1) {
        s1 += __shfl_xor_sync(0xffffffffu, s1, o);
        s2 += __shfl_xor_sync(0xffffffffu, s2, o);
    }
    float mean = s1 * (1.0f / 256.0f);
    float var = (s2 - 256.0f * mean * mean) * (1.0f / 255.0f);
    float inv = 1.0f / sqrtf(var);
#pragma unroll
    for (int j = 0; j < 9; j++) {
        int ch = lane + 32 * j;
        if (ch >= 4 && ch < 260)
            out[OFF_DESC + (size_t)(b * C_ + (ch - 4)) * N_ + n] =
                (vals[j] - mean) * inv;
    }
}

// ---------------------------------------------------------------------------
extern "C" void kernel_launch(void* const* d_in, const int* in_sizes, int n_in,
                              void* d_out, int out_size) {
    const float* tgt_coords = (const float*)d_in[1];
    const float* tgt_w      = (const float*)d_in[3];
    const float* src        = (const float*)d_in[5];
    const float* tgt_desc   = (const float*)d_in[6];
    float* out = (float*)d_out;

    cudaFuncSetAttribute(flash_kernel,
                         cudaFuncAttributeMaxDynamicSharedMemorySize,
                         160 * 1024);

    init_kernel<<<1, 32>>>(out);
    stats_kernel<<<(B_ * M_ + 255) / 256, 256>>>(tgt_desc);
    srcsum_kernel<<<(B_ * N_ + 255) / 256, 256>>>(src);
    flash_kernel<<<B_ * SPLITS * NT, 256, 152576>>>(src, tgt_desc,
                                                    tgt_coords, tgt_w);
    combine_kernel<<<(B_ * N_) / 8, 256>>>(out);
}

// round 3
// speedup vs baseline: 1.0041x; 1.0041x over previous
#include <cuda_runtime.h>
#include <math_constants.h>
#include <cstdint>

// ---------------------------------------------------------------------------
// SoftmaxMatcherBlock: fused flash-attention-style matcher.
//   B=2, C=256, N=1024 (queries), M=65536 (keys), V-dim = 260 (3+1+256).
// Pipeline:
//   init_kernel   : zero the max_softmax slots
//   stats_kernel  : per-key mean + alpha = 100/(256*std) (ddof=1)
//   srcsum_kernel : per-query sum over C of src (for exact mean-correction)
//   flash_kernel  : split-M online softmax; logits fp32 GEMM + P@V fp32 GEMM
//   combine_kernel: merge splits, normalize, zn(desc), 2D proj, valid, maxsoft
//
// Algebra: logit(n,m) = alpha_m * (dot(src_n, tgt_m) - mu_m * sum_c src_cn)
// with alpha_m = (1/0.01) / (C * std_m). This avoids materializing the
// normalized key matrix and the 512 MiB score matrix.
// ---------------------------------------------------------------------------

#define B_ 2
#define C_ 256
#define N_ 1024
#define M_ 65536
#define BN 64
#define BM 128
#define SPLITS 8
#define NT (N_ / BN)            // 16
#define MSLICE (M_ / SPLITS)    // 8192
#define ITERS (MSLICE / BM)     // 64
#define VD 272                  // 260 real channels padded to 272 (4*68)
#define VD2 274                 // mu, Z, 272 accum
#define PS_STRIDE 132           // P tile row stride (pad to kill bank conflicts)

#define OFF_COORDS 0
#define OFF_W      6144
#define OFF_DESC   8192
#define OFF_2D     532480
#define OFF_VALID  536576
#define OFF_MAX    538624

#define CART_MIN 33.048f        // (256/2 - 0.5) * 0.2592
#define RES_     0.2592f

// Device scratch (static allocations are allowed; cudaMalloc is not).
__device__ float g_alpha[B_ * M_];
__device__ float g_mu[B_ * M_];
__device__ float g_ssum[B_ * N_];
__device__ float g_part[(size_t)B_ * SPLITS * NT * BN * VD2];  // ~17 MiB

// ---------------------------------------------------------------------------
__global__ void init_kernel(float* __restrict__ out) {
    if (threadIdx.x < 2) out[OFF_MAX + threadIdx.x] = 0.0f;
}

// Per (b,m): mean over C and alpha = (100/256)/std (ddof=1).
__global__ void stats_kernel(const float* __restrict__ tgt_desc) {
    int gid = blockIdx.x * blockDim.x + threadIdx.x;
    if (gid >= B_ * M_) return;
    int b = gid / M_;
    int m = gid - b * M_;
    const float* p = tgt_desc + (size_t)b * C_ * M_ + m;
    float s = 0.f, s2 = 0.f;
#pragma unroll 8
    for (int c = 0; c < C_; c++) {
        float t = p[(size_t)c * M_];
        s += t;
        s2 += t * t;
    }
    float mean = s * (1.0f / C_);
    float var = (s2 - (float)C_ * mean * mean) * (1.0f / (C_ - 1));
    g_mu[gid] = mean;
    g_alpha[gid] = (100.0f / C_) / sqrtf(var);
}

// Per (b,n): sum over C of src_desc_norm (tiny mean-correction term).
__global__ void srcsum_kernel(const float* __restrict__ src) {
    int gid = blockIdx.x * blockDim.x + threadIdx.x;
    if (gid >= B_ * N_) return;
    int b = gid / N_;
    int n = gid - b * N_;
    const float* p = src + (size_t)b * C_ * N_ + n;
    float s = 0.f;
#pragma unroll 8
    for (int c = 0; c < C_; c++) s += p[(size_t)c * N_];
    g_ssum[gid] = s;
}

// ---------------------------------------------------------------------------
// Fused flash kernel. Grid: B * SPLITS * NT CTAs of 256 threads.
// smem (floats):
//   Ss   [C][BN]       16384      persistent query tile
//   Ts   [32][BM]       4096      staged key chunk (K-major)
//   Ps   [BN][132]      8448      exp(P) tile
//   Vs   [32][VD]       8704      staged V chunk
//   alpha/mu/ssum/rowMu/rowZ/fsc  small
__global__ void __launch_bounds__(256, 1)
flash_kernel(const float* __restrict__ src,
             const float* __restrict__ tgt_desc,
             const float* __restrict__ tgt_coords,
             const float* __restrict__ tgt_w) {
    extern __shared__ float sm[];
    float* Ss      = sm;                 // 16384
    float* Ts      = sm + 16384;         // 4096
    float* Ps      = sm + 20480;         // 8448
    float* Vs      = sm + 28928;         // 8704
    float* alpha_s = sm + 37632;         // 128
    float* mu_s    = sm + 37760;         // 128
    float* ssum_s  = sm + 37888;         // 64
    float* rowMu   = sm + 37952;         // 64
    float* rowZ    = sm + 38016;         // 64
    float* fsc     = sm + 38080;         // 64  (total 38144 floats = 152576 B)

    const int tid = threadIdx.x;
    const int bid = blockIdx.x;
    const int bb  = bid / (SPLITS * NT);
    const int rem = bid - bb * (SPLITS * NT);
    const int sp  = rem / NT;
    const int nt  = rem - sp * NT;
    const int n0  = nt * BN;
    const int mbase = sp * MSLICE;

    const int tx = tid & 15;   // m-dir (8 cols each)
    const int ty = tid >> 4;   // n-dir (4 rows each)
    const int n2 = tid >> 2;   // GEMM2 row (0..63)
    const int g  = tid & 3;    // GEMM2 col group (68 cols each)

    // Load persistent query tile Ss[c][j] = src[bb][c][n0+j]
    {
        const float* spp = src + (size_t)bb * C_ * N_ + n0;
        for (int i = tid; i < (C_ * BN) / 4; i += 256) {
            int f = i * 4;
            int c = f >> 6;
            int j = f & 63;
            *(float4*)&Ss[c * BN + j] = *(const float4*)&spp[(size_t)c * N_ + j];
        }
    }
    if (tid < BN) {
        ssum_s[tid] = g_ssum[bb * N_ + n0 + tid];
        rowMu[tid] = -CUDART_INF_F;
        rowZ[tid] = 0.0f;
    }

    float O[68];
#pragma unroll
    for (int j = 0; j < 68; j++) O[j] = 0.0f;
    __syncthreads();

    for (int it = 0; it < ITERS; it++) {
        const int m0 = mbase + it * BM;
        if (tid < BM) alpha_s[tid] = g_alpha[bb * M_ + m0 + tid];
        else          mu_s[tid - BM] = g_mu[bb * M_ + m0 + (tid - BM)];

        // ---- GEMM1: L[64][128] = Ss^T(64x256) * Ts(256x128) ----
        float L[4][8];
#pragma unroll
        for (int r = 0; r < 4; r++)
#pragma unroll
            for (int u = 0; u < 8; u++) L[r][u] = 0.0f;

        const float* tg0 = tgt_desc + (size_t)bb * C_ * M_ + m0;
#pragma unroll 1
        for (int kc = 0; kc < C_ / 32; kc++) {
            __syncthreads();
            const float* tg = tg0 + (size_t)kc * 32 * M_;
            // 4 x LDG.128 per thread, front-batched for MLP
            {
                int f0 = tid * 4;
#pragma unroll
                for (int q = 0; q < 4; q++) {
                    int f = f0 + q * 1024;
                    int kk = f >> 7;
                    int mm = f & 127;
                    *(float4*)&Ts[kk * BM + mm] =
                        *(const float4*)&tg[(size_t)kk * M_ + mm];
                }
            }
            __syncthreads();
#pragma unroll
            for (int k = 0; k < 32; k++) {
                float4 a4 = *(float4*)&Ss[(kc * 32 + k) * BN + (ty << 2)];
                float4 b4 = *(float4*)&Ts[k * BM + (tx << 3)];
                float4 b5 = *(float4*)&Ts[k * BM + (tx << 3) + 4];
                float av[4] = {a4.x, a4.y, a4.z, a4.w};
                float bv[8] = {b4.x, b4.y, b4.z, b4.w, b5.x, b5.y, b5.z, b5.w};
#pragma unroll
                for (int r = 0; r < 4; r++)
#pragma unroll
                    for (int u = 0; u < 8; u++) L[r][u] += av[r] * bv[u];
            }
        }

        // ---- finalize logits + online softmax (per row, across 16 tx) ----
#pragma unroll
        for (int r = 0; r < 4; r++) {
            int row = (ty << 2) + r;
            float ssn = ssum_s[row];
            float lv[8];
            float mloc = -CUDART_INF_F;
#pragma unroll
            for (int u = 0; u < 8; u++) {
                int cm = (tx << 3) + u;
                float l = alpha_s[cm] * (L[r][u] - mu_s[cm] * ssn);
                lv[u] = l;
                mloc = fmaxf(mloc, l);
            }
#pragma unroll
            for (int o = 8; o > 0; o >>= 1)
                mloc = fmaxf(mloc, __shfl_xor_sync(0xffffffffu, mloc, o, 16));
            float mold = rowMu[row];
            float mnew = fmaxf(mold, mloc);
            float sloc = 0.0f;
#pragma unroll
            for (int u = 0; u < 8; u++) {
                float p = __expf(lv[u] - mnew);
                Ps[row * PS_STRIDE + (tx << 3) + u] = p;
                sloc += p;
            }
#pragma unroll
            for (int o = 8; o > 0; o >>= 1)
                sloc += __shfl_xor_sync(0xffffffffu, sloc, o, 16);
            if (tx == 0) {
                float fr = __expf(mold - mnew);   // 0 on first tile (-inf)
                rowZ[row] = rowZ[row] * fr + sloc;
                rowMu[row] = mnew;
                fsc[row] = fr;
            }
        }
        __syncthreads();

        // ---- GEMM2: O[64][272] = f*O + Ps[64][128] * V[128][272] ----
        {
            float fr = fsc[n2];
#pragma unroll
            for (int j = 0; j < 68; j++) O[j] *= fr;
        }
        const int lane = tid & 31;
        const int grp = tid >> 5;
#pragma unroll 1
        for (int ck = 0; ck < 4; ck++) {
            int mg = m0 + ck * 32 + lane;
            for (int ch = grp; ch < VD; ch += 8) {
                float v;
                if (ch < 3)        v = tgt_coords[((size_t)bb * 3 + ch) * M_ + mg];
                else if (ch == 3)  v = tgt_w[(size_t)bb * M_ + mg];
                else if (ch < 260) v = tgt_desc[((size_t)bb * C_ + (ch - 4)) * M_ + mg];
                else               v = 0.0f;
                Vs[lane * VD + ch] = v;
            }
            __syncthreads();
            const float* prow = &Ps[n2 * PS_STRIDE + ck * 32];
#pragma unroll
            for (int mm = 0; mm < 32; mm++) {
                float p = prow[mm];
                const float4* vr = (const float4*)&Vs[mm * VD + g * 68];
#pragma unroll
                for (int jj = 0; jj < 17; jj++) {
                    float4 v = vr[jj];
                    O[jj * 4 + 0] += p * v.x;
                    O[jj * 4 + 1] += p * v.y;
                    O[jj * 4 + 2] += p * v.z;
                    O[jj * 4 + 3] += p * v.w;
                }
            }
            __syncthreads();
        }
    }

    // ---- write partials ----
    size_t rowidx = (((size_t)bb * SPLITS + sp) * NT + nt) * BN + n2;
    float* pp = g_part + rowidx * VD2;
    if (g == 0) {
        pp[0] = rowMu[n2];
        pp[1] = rowZ[n2];
    }
#pragma unroll
    for (int jj = 0; jj < 68; jj++) pp[2 + g * 68 + jj] = O[jj];
}

// ---------------------------------------------------------------------------
// Combine splits + all epilogue math. One warp per (b,n) row.
__global__ void combine_kernel(float* __restrict__ out) {
    const int warp = threadIdx.x >> 5;
    const int lane = threadIdx.x & 31;
    const int row = blockIdx.x * 8 + warp;      // 0..2047
    const int b = row / N_;
    const int n = row - b * N_;
    const int nt = n / BN;
    const int r = n - nt * BN;

    const float* pbase[SPLITS];
    float mu[SPLITS], Zv[SPLITS];
#pragma unroll
    for (int s = 0; s < SPLITS; s++) {
        pbase[s] = g_part +
            ((((size_t)b * SPLITS + s) * NT + nt) * BN + r) * VD2;
        mu[s] = pbase[s][0];
        Zv[s] = pbase[s][1];
    }
    float gmax = mu[0];
#pragma unroll
    for (int s = 1; s < SPLITS; s++) gmax = fmaxf(gmax, mu[s]);
    float w[SPLITS], Zt = 0.0f;
#pragma unroll
    for (int s = 0; s < SPLITS; s++) {
        w[s] = __expf(mu[s] - gmax);
        Zt += Zv[s] * w[s];
    }
    float invZ = 1.0f / Zt;

    float vals[9];
#pragma unroll
    for (int j = 0; j < 9; j++) {
        int ch = lane + 32 * j;
        float acc = 0.0f;
        if (ch < VD) {
#pragma unroll
            for (int s = 0; s < SPLITS; s++)
                acc += w[s] * pbase[s][2 + ch];
        }
        vals[j] = acc * invZ;
    }

    // coords / weight / 2D / valid / max_softmax
    if (lane < 3) out[OFF_COORDS + (b * 3 + lane) * N_ + n] = vals[0];
    if (lane == 3) out[OFF_W + b * N_ + n] = vals[0];
    float x = __shfl_sync(0xffffffffu, vals[0], 0);
    float y = __shfl_sync(0xffffffffu, vals[0], 1);
    if (lane == 0) {
        out[OFF_2D + (b * N_ + n) * 2 + 0] = (CART_MIN + y) / RES_;
        out[OFF_2D + (b * N_ + n) * 2 + 1] = (CART_MIN - x) / RES_;
    }
    if (lane == 4) out[OFF_VALID + b * N_ + n] = 1.0f;
    if (lane == 5)
        atomicMax((int*)(out + OFF_MAX + b), __float_as_int(invZ));

    // zn over the 256 desc channels (ch in [4,260)); ddof=1
    float s1 = 0.0f, s2 = 0.0f;
#pragma unroll
    for (int j = 0; j < 9; j++) {
        int ch = lane + 32 * j;
        if (ch >= 4 && ch < 260) {
            s1 += vals[j];
            s2 += vals[j] * vals[j];
        }
    }
#pragma unroll
    for (int o = 16; o > 0; o >>= 1) {
        s1 += __shfl_xor_sync(0xffffffffu, s1, o);
        s2 += __shfl_xor_sync(0xffffffffu, s2, o);
    }
    float mean = s1 * (1.0f / 256.0f);
    float var = (s2 - 256.0f * mean * mean) * (1.0f / 255.0f);
    float inv = 1.0f / sqrtf(var);
#pragma unroll
    for (int j = 0; j < 9; j++) {
        int ch = lane + 32 * j;
        if (ch >= 4 && ch < 260)
            out[OFF_DESC + (size_t)(b * C_ + (ch - 4)) * N_ + n] =
                (vals[j] - mean) * inv;
    }
}

// ---------------------------------------------------------------------------
extern "C" void kernel_launch(void* const* d_in, const int* in_sizes, int n_in,
                              void* d_out, int out_size) {
    const float* tgt_coords = (const float*)d_in[1];
    const float* tgt_w      = (const float*)d_in[3];
    const float* src        = (const float*)d_in[5];
    const float* tgt_desc   = (const float*)d_in[6];
    float* out = (float*)d_out;

    cudaFuncSetAttribute(flash_kernel,
                         cudaFuncAttributeMaxDynamicSharedMemorySize,
                         160 * 1024);

    init_kernel<<<1, 32>>>(out);
    stats_kernel<<<(B_ * M_ + 255) / 256, 256>>>(tgt_desc);
    srcsum_kernel<<<(B_ * N_ + 255) / 256, 256>>>(src);
    flash_kernel<<<B_ * SPLITS * NT, 256, 152576>>>(src, tgt_desc,
                                                    tgt_coords, tgt_w);
    combine_kernel<<<(B_ * N_) / 8, 256>>>(out);
}

// round 5
// speedup vs baseline: 1.0480x; 1.0437x over previous
#include <cuda_runtime.h>
#include <math_constants.h>
#include <cstdint>

// ---------------------------------------------------------------------------
// SoftmaxMatcherBlock: fused flash-attention-style matcher.
//   B=2, C=256, N=1024 (queries), M=65536 (keys), V-dim = 260 (3+1+256).
// R3/R4 changes vs R2 (9545us baseline, L1=76%/fma=20%):
//   * packed fma.rn.f32x2 in both GEMM inner loops (3-reg FFMA is half-rate
//     on sm_100; packed form restores full 128 FMA/cyc/SM and halves LDS count)
//   * SPLITS 8 -> 4: grid 256 -> 128 CTAs = exactly one wave on 148 SMs
//   * double-buffered Ts with register prefetch: 1 sync/chunk, LDG overlapped
// ---------------------------------------------------------------------------

#define B_ 2
#define C_ 256
#define N_ 1024
#define M_ 65536
#define BN 64
#define BM 128
#define SPLITS 4
#define NT (N_ / BN)            // 16
#define MSLICE (M_ / SPLITS)    // 16384
#define ITERS (MSLICE / BM)     // 128
#define VD 272                  // 260 real channels padded to 272 (4*68)
#define VD2 274                 // mu, Z, 272 accum
#define PS_STRIDE 132           // P tile row stride (pad to kill bank conflicts)

#define OFF_COORDS 0
#define OFF_W      6144
#define OFF_DESC   8192
#define OFF_2D     532480
#define OFF_VALID  536576
#define OFF_MAX    538624

#define CART_MIN 33.048f        // (256/2 - 0.5) * 0.2592
#define RES_     0.2592f

typedef unsigned long long u64t;

__device__ __forceinline__ u64t splat2(float x) {
    u64t r;
    asm("mov.b64 %0, {%1, %1};" : "=l"(r) : "f"(x));
    return r;
}
__device__ __forceinline__ void fma2(u64t& d, u64t a, u64t b) {
    asm("fma.rn.f32x2 %0, %1, %2, %0;" : "+l"(d) : "l"(a), "l"(b));
}
__device__ __forceinline__ void mul2(u64t& d, u64t a) {
    asm("mul.rn.f32x2 %0, %0, %1;" : "+l"(d) : "l"(a));
}
__device__ __forceinline__ float2 unpack2(u64t v) {
    float2 f;
    asm("mov.b64 {%0, %1}, %2;" : "=f"(f.x), "=f"(f.y) : "l"(v));
    return f;
}

// Device scratch (static allocations are allowed; cudaMalloc is not).
__device__ float g_alpha[B_ * M_];
__device__ float g_mu[B_ * M_];
__device__ float g_ssum[B_ * N_];
__device__ float g_part[(size_t)B_ * SPLITS * NT * BN * VD2];  // ~9 MiB

// ---------------------------------------------------------------------------
__global__ void init_kernel(float* __restrict__ out) {
    if (threadIdx.x < 2) out[OFF_MAX + threadIdx.x] = 0.0f;
}

// Per (b,m): mean over C and alpha = (100/256)/std (ddof=1).
__global__ void stats_kernel(const float* __restrict__ tgt_desc) {
    int gid = blockIdx.x * blockDim.x + threadIdx.x;
    if (gid >= B_ * M_) return;
    int b = gid / M_;
    int m = gid - b * M_;
    const float* p = tgt_desc + (size_t)b * C_ * M_ + m;
    float s = 0.f, s2 = 0.f;
#pragma unroll 8
    for (int c = 0; c < C_; c++) {
        float t = p[(size_t)c * M_];
        s += t;
        s2 += t * t;
    }
    float mean = s * (1.0f / C_);
    float var = (s2 - (float)C_ * mean * mean) * (1.0f / (C_ - 1));
    g_mu[gid] = mean;
    g_alpha[gid] = (100.0f / C_) / sqrtf(var);
}

// Per (b,n): sum over C of src_desc_norm (tiny mean-correction term).
__global__ void srcsum_kernel(const float* __restrict__ src) {
    int gid = blockIdx.x * blockDim.x + threadIdx.x;
    if (gid >= B_ * N_) return;
    int b = gid / N_;
    int n = gid - b * N_;
    const float* p = src + (size_t)b * C_ * N_ + n;
    float s = 0.f;
#pragma unroll 8
    for (int c = 0; c < C_; c++) s += p[(size_t)c * N_];
    g_ssum[gid] = s;
}

// ---------------------------------------------------------------------------
// Fused flash kernel. Grid: B * SPLITS * NT = 128 CTAs of 256 threads.
// smem (floats):
//   Ss   [C][BN]       16384   persistent query tile (64 KB)
//   Ts   2x[32][BM]     8192   double-buffered key chunk (32 KB)
//   Ps   [BN][132]      8448   exp(P) tile (33 KB)
//   Vs   [32][VD]       8704   staged V chunk (34 KB)
//   alpha/mu/ssum/rowMu/rowZ/fsc small
__global__ void __launch_bounds__(256, 1)
flash_kernel(const float* __restrict__ src,
             const float* __restrict__ tgt_desc,
             const float* __restrict__ tgt_coords,
             const float* __restrict__ tgt_w) {
    extern __shared__ float sm[];
    float* Ss      = sm;                 // 16384 floats
    float* Ts      = sm + 16384;         // 8192 floats (2 x 4096)
    float* Ps      = sm + 24576;         // 8448
    float* Vs      = sm + 33024;         // 8704
    float* alpha_s = sm + 41728;         // 128
    float* mu_s    = sm + 41856;         // 128
    float* ssum_s  = sm + 41984;         // 64
    float* rowMu   = sm + 42048;         // 64
    float* rowZ    = sm + 42112;         // 64
    float* fsc     = sm + 42176;         // 64  -> 42240 floats = 168960 B

    const int tid = threadIdx.x;
    const int bid = blockIdx.x;
    const int bb  = bid / (SPLITS * NT);
    const int rem = bid - bb * (SPLITS * NT);
    const int sp  = rem / NT;
    const int nt  = rem - sp * NT;
    const int n0  = nt * BN;
    const int mbase = sp * MSLICE;

    const int tx = tid & 15;   // m-dir (8 cols each)
    const int ty = tid >> 4;   // n-dir (4 rows each)
    const int n2 = tid >> 2;   // GEMM2 row (0..63)
    const int g  = tid & 3;    // GEMM2 col group (68 cols each)

    // Load persistent query tile Ss[c][j] = src[bb][c][n0+j]
    {
        const float* spp = src + (size_t)bb * C_ * N_ + n0;
        for (int i = tid; i < (C_ * BN) / 4; i += 256) {
            int f = i * 4;
            int c = f >> 6;
            int j = f & 63;
            *(float4*)&Ss[c * BN + j] = *(const float4*)&spp[(size_t)c * N_ + j];
        }
    }
    if (tid < BN) {
        ssum_s[tid] = g_ssum[bb * N_ + n0 + tid];
        rowMu[tid] = -CUDART_INF_F;
        rowZ[tid] = 0.0f;
    }

    u64t O2[34];
#pragma unroll
    for (int j = 0; j < 34; j++) O2[j] = 0ull;
    __syncthreads();

    // Per-thread chunk staging indices (4 x float4 per 32x128 chunk)
    const int st_k = (tid * 4) >> 7;      // 0..7 base row (q adds 8)
    const int st_m = (tid * 4) & 127;     // col

#pragma unroll 1
    for (int it = 0; it < ITERS; it++) {
        const int m0 = mbase + it * BM;
        if (tid < BM) alpha_s[tid] = g_alpha[bb * M_ + m0 + tid];
        else          mu_s[tid - BM] = g_mu[bb * M_ + m0 + (tid - BM)];

        // ---- GEMM1: L[64][128] = Ss^T(64x256) * Ts(256x128), packed f32x2 ----
        u64t L2[4][4];
#pragma unroll
        for (int r = 0; r < 4; r++)
#pragma unroll
            for (int p = 0; p < 4; p++) L2[r][p] = 0ull;

        const float* tg0 = tgt_desc + (size_t)bb * C_ * M_ + m0;
        float4 pf[4];
        // prefetch chunk 0 and stage
        {
            const float* tg = tg0;
#pragma unroll
            for (int q = 0; q < 4; q++)
                pf[q] = *(const float4*)&tg[(size_t)(st_k + q * 8) * M_ + st_m];
            float* buf = Ts;
#pragma unroll
            for (int q = 0; q < 4; q++)
                *(float4*)&buf[(st_k + q * 8) * BM + st_m] = pf[q];
        }

#pragma unroll 1
        for (int kc = 0; kc < 8; kc++) {
            if (kc < 7) {
                const float* tg = tg0 + (size_t)((kc + 1) * 32) * M_;
#pragma unroll
                for (int q = 0; q < 4; q++)
                    pf[q] = *(const float4*)&tg[(size_t)(st_k + q * 8) * M_ + st_m];
            }
            __syncthreads();   // Ts[kc&1] ready; prior compute on other buf done
            const float* cur = Ts + (kc & 1) * 4096;
#pragma unroll 16
            for (int k = 0; k < 32; k++) {
                float4 a4 = *(const float4*)&Ss[(kc * 32 + k) * BN + (ty << 2)];
                ulonglong2 b01 = *(const ulonglong2*)&cur[k * BM + (tx << 3)];
                ulonglong2 b23 = *(const ulonglong2*)&cur[k * BM + (tx << 3) + 4];
                u64t a0 = splat2(a4.x), a1 = splat2(a4.y);
                u64t a2 = splat2(a4.z), a3 = splat2(a4.w);
                fma2(L2[0][0], a0, b01.x); fma2(L2[0][1], a0, b01.y);
                fma2(L2[0][2], a0, b23.x); fma2(L2[0][3], a0, b23.y);
                fma2(L2[1][0], a1, b01.x); fma2(L2[1][1], a1, b01.y);
                fma2(L2[1][2], a1, b23.x); fma2(L2[1][3], a1, b23.y);
                fma2(L2[2][0], a2, b01.x); fma2(L2[2][1], a2, b01.y);
                fma2(L2[2][2], a2, b23.x); fma2(L2[2][3], a2, b23.y);
                fma2(L2[3][0], a3, b01.x); fma2(L2[3][1], a3, b01.y);
                fma2(L2[3][2], a3, b23.x); fma2(L2[3][3], a3, b23.y);
            }
            if (kc < 7) {
                float* buf = Ts + ((kc + 1) & 1) * 4096;
#pragma unroll
                for (int q = 0; q < 4; q++)
                    *(float4*)&buf[(st_k + q * 8) * BM + st_m] = pf[q];
            }
        }

        // ---- finalize logits + online softmax (per row, across 16 tx) ----
#pragma unroll
        for (int r = 0; r < 4; r++) {
            int row = (ty << 2) + r;
            float ssn = ssum_s[row];
            float lv[8];
#pragma unroll
            for (int p = 0; p < 4; p++) {
                float2 f = unpack2(L2[r][p]);
                lv[2 * p] = f.x;
                lv[2 * p + 1] = f.y;
            }
            float mloc = -CUDART_INF_F;
#pragma unroll
            for (int u = 0; u < 8; u++) {
                int cm = (tx << 3) + u;
                float l = alpha_s[cm] * (lv[u] - mu_s[cm] * ssn);
                lv[u] = l;
                mloc = fmaxf(mloc, l);
            }
#pragma unroll
            for (int o = 8; o > 0; o >>= 1)
                mloc = fmaxf(mloc, __shfl_xor_sync(0xffffffffu, mloc, o, 16));
            float mold = rowMu[row];
            float mnew = fmaxf(mold, mloc);
            float sloc = 0.0f;
#pragma unroll
            for (int u = 0; u < 8; u++) {
                float p = __expf(lv[u] - mnew);
                Ps[row * PS_STRIDE + (tx << 3) + u] = p;
                sloc += p;
            }
#pragma unroll
            for (int o = 8; o > 0; o >>= 1)
                sloc += __shfl_xor_sync(0xffffffffu, sloc, o, 16);
            if (tx == 0) {
                float fr = __expf(mold - mnew);   // 0 on first tile (-inf)
                rowZ[row] = rowZ[row] * fr + sloc;
                rowMu[row] = mnew;
                fsc[row] = fr;
            }
        }
        __syncthreads();

        // ---- GEMM2: O[64][272] = f*O + Ps[64][128] * V[128][272], packed ----
        {
            u64t fr2 = splat2(fsc[n2]);
#pragma unroll
            for (int j = 0; j < 34; j++) mul2(O2[j], fr2);
        }
        const int lane = tid & 31;
        const int grp = tid >> 5;
#pragma unroll 1
        for (int ck = 0; ck < 4; ck++) {
            int mg = m0 + ck * 32 + lane;
            for (int ch = grp; ch < VD; ch += 8) {
                float v;
                if (ch < 3)        v = tgt_coords[((size_t)bb * 3 + ch) * M_ + mg];
                else if (ch == 3)  v = tgt_w[(size_t)bb * M_ + mg];
                else if (ch < 260) v = tgt_desc[((size_t)bb * C_ + (ch - 4)) * M_ + mg];
                else               v = 0.0f;
                Vs[lane * VD + ch] = v;
            }
            __syncthreads();
            const float* prow = &Ps[n2 * PS_STRIDE + ck * 32];
#pragma unroll 8
            for (int mm = 0; mm < 32; mm++) {
                u64t p2 = splat2(prow[mm]);
                const ulonglong2* vr = (const ulonglong2*)&Vs[mm * VD + g * 68];
#pragma unroll
                for (int jj = 0; jj < 17; jj++) {
                    ulonglong2 v = vr[jj];
                    fma2(O2[2 * jj], p2, v.x);
                    fma2(O2[2 * jj + 1], p2, v.y);
                }
            }
            __syncthreads();
        }
    }

    // ---- write partials ----
    size_t rowidx = (((size_t)bb * SPLITS + sp) * NT + nt) * BN + n2;
    float* pp = g_part + rowidx * VD2;
    if (g == 0) {
        pp[0] = rowMu[n2];
        pp[1] = rowZ[n2];
    }
#pragma unroll
    for (int jj = 0; jj < 34; jj++) {
        float2 f = unpack2(O2[jj]);
        pp[2 + g * 68 + 2 * jj] = f.x;
        pp[2 + g * 68 + 2 * jj + 1] = f.y;
    }
}

// ---------------------------------------------------------------------------
// Combine splits + all epilogue math. One warp per (b,n) row.
__global__ void combine_kernel(float* __restrict__ out) {
    const int warp = threadIdx.x >> 5;
    const int lane = threadIdx.x & 31;
    const int row = blockIdx.x * 8 + warp;      // 0..2047
    const int b = row / N_;
    const int n = row - b * N_;
    const int nt = n / BN;
    const int r = n - nt * BN;

    const float* pbase[SPLITS];
    float mu[SPLITS], Zv[SPLITS];
#pragma unroll
    for (int s = 0; s < SPLITS; s++) {
        pbase[s] = g_part +
            ((((size_t)b * SPLITS + s) * NT + nt) * BN + r) * VD2;
        mu[s] = pbase[s][0];
        Zv[s] = pbase[s][1];
    }
    float gmax = mu[0];
#pragma unroll
    for (int s = 1; s < SPLITS; s++) gmax = fmaxf(gmax, mu[s]);
    float w[SPLITS], Zt = 0.0f;
#pragma unroll
    for (int s = 0; s < SPLITS; s++) {
        w[s] = __expf(mu[s] - gmax);
        Zt += Zv[s] * w[s];
    }
    float invZ = 1.0f / Zt;

    float vals[9];
#pragma unroll
    for (int j = 0; j < 9; j++) {
        int ch = lane + 32 * j;
        float acc = 0.0f;
        if (ch < VD) {
#pragma unroll
            for (int s = 0; s < SPLITS; s++)
                acc += w[s] * pbase[s][2 + ch];
        }
        vals[j] = acc * invZ;
    }

    // coords / weight / 2D / valid / max_softmax
    if (lane < 3) out[OFF_COORDS + (b * 3 + lane) * N_ + n] = vals[0];
    if (lane == 3) out[OFF_W + b * N_ + n] = vals[0];
    float x = __shfl_sync(0xffffffffu, vals[0], 0);
    float y = __shfl_sync(0xffffffffu, vals[0], 1);
    if (lane == 0) {
        out[OFF_2D + (b * N_ + n) * 2 + 0] = (CART_MIN + y) / RES_;
        out[OFF_2D + (b * N_ + n) * 2 + 1] = (CART_MIN - x) / RES_;
    }
    if (lane == 4) out[OFF_VALID + b * N_ + n] = 1.0f;
    if (lane == 5)
        atomicMax((int*)(out + OFF_MAX + b), __float_as_int(invZ));

    // zn over the 256 desc channels (ch in [4,260)); ddof=1
    float s1 = 0.0f, s2 = 0.0f;
#pragma unroll
    for (int j = 0; j < 9; j++) {
        int ch = lane + 32 * j;
        if (ch >= 4 && ch < 260) {
            s1 += vals[j];
            s2 += vals[j] * vals[j];
        }
    }
#pragma unroll
    for (int o = 16; o > 0; o >>= 1) {
        s1 += __shfl_xor_sync(0xffffffffu, s1, o);
        s2 += __shfl_xor_sync(0xffffffffu, s2, o);
    }
    float mean = s1 * (1.0f / 256.0f);
    float var = (s2 - 256.0f * mean * mean) * (1.0f / 255.0f);
    float inv = 1.0f / sqrtf(var);
#pragma unroll
    for (int j = 0; j < 9; j++) {
        int ch = lane + 32 * j;
        if (ch >= 4 && ch < 260)
            out[OFF_DESC + (size_t)(b * C_ + (ch - 4)) * N_ + n] =
                (vals[j] - mean) * inv;
    }
}

// ---------------------------------------------------------------------------
extern "C" void kernel_launch(void* const* d_in, const int* in_sizes, int n_in,
                              void* d_out, int out_size) {
    const float* tgt_coords = (const float*)d_in[1];
    const float* tgt_w      = (const float*)d_in[3];
    const float* src        = (const float*)d_in[5];
    const float* tgt_desc   = (const float*)d_in[6];
    float* out = (float*)d_out;

    cudaFuncSetAttribute(flash_kernel,
                         cudaFuncAttributeMaxDynamicSharedMemorySize,
                         176 * 1024);

    init_kernel<<<1, 32>>>(out);
    stats_kernel<<<(B_ * M_ + 255) / 256, 256>>>(tgt_desc);
    srcsum_kernel<<<(B_ * N_ + 255) / 256, 256>>>(src);
    flash_kernel<<<B_ * SPLITS * NT, 256, 168960>>>(src, tgt_desc,
                                                    tgt_coords, tgt_w);
    combine_kernel<<<(B_ * N_) / 8, 256>>>(out);
}